// round 10
// baseline (speedup 1.0000x reference)
#include <cuda_runtime.h>
#include <cuda_bf16.h>
#include <cuda_fp16.h>
#include <cstdint>

#define BATCH   1024
#define TWO_B   2048
#define DFLAT   16384
#define NBLK    16
#define NCTA    272
#define FP8_SCALE 128.f
#define INV_ACC   (1.f / 16384.f)

// ---------------- scratch ----------------
__device__ uint8_t g_rn[(size_t)TWO_B * DFLAT];   // 32 MB e4m3 (L2-resident)
__device__ float   g_row[TWO_B];
__device__ float   g_pos[TWO_B];
__device__ int     g_done;

// ---------------- helpers ----------------
__device__ __forceinline__ uint32_t smem_u32(const void* p) {
    return (uint32_t)__cvta_generic_to_shared(p);
}
__device__ __forceinline__ void cpasync16(uint32_t s, const void* g) {
    asm volatile("cp.async.ca.shared.global [%0], [%1], 16;\n" :: "r"(s), "l"(g));
}
#define CP_COMMIT() asm volatile("cp.async.commit_group;\n")
#define CP_WAIT(N)  asm volatile("cp.async.wait_group %0;\n" :: "n"(N))

#define LDSM4(r0, r1, r2, r3, a) \
    asm volatile("ldmatrix.sync.aligned.m8n8.x4.shared.b16 {%0,%1,%2,%3}, [%4];" \
                 : "=r"(r0), "=r"(r1), "=r"(r2), "=r"(r3) : "r"(a))

// fp8 e4m3 mma with f16 accumulators (fastest register path measured on sm_103a)
__device__ __forceinline__ void mma16832h(uint32_t* c, const uint32_t* a, uint32_t b0, uint32_t b1) {
    asm volatile(
        "mma.sync.aligned.m16n8k32.row.col.f16.e4m3.e4m3.f16 "
        "{%0,%1}, {%2,%3,%4,%5}, {%6,%7}, {%0,%1};\n"
        : "+r"(c[0]), "+r"(c[1])
        : "r"(a[0]), "r"(a[1]), "r"(a[2]), "r"(a[3]), "r"(b0), "r"(b1));
}

__device__ __forceinline__ uint32_t f2_e4m3x2(float hi, float lo) {
    uint16_t r;
    asm volatile("cvt.rn.satfinite.e4m3x2.f32 %0, %1, %2;" : "=h"(r) : "f"(hi), "f"(lo));
    return (uint32_t)r;
}

// ---------------- kernel 1: fused double normalization -> scaled e4m3 ----------------
__global__ void __launch_bounds__(256) nrm_kernel(const float* __restrict__ ei,
                                                  const float* __restrict__ ej) {
    const int b = blockIdx.x;
    const float* src = (b < BATCH) ? (ei + (size_t)b * DFLAT)
                                   : (ej + (size_t)(b - BATCH) * DFLAT);
    const int tid = threadIdx.x;
    const int w = tid >> 5, lane = tid & 31;
    const int c4 = lane * 4;
    const int r0 = w * 16;
    if (tid == 0) g_row[b] = 0.f;

    __nv_bfloat162 rbuf[32];
    float4 s4 = make_float4(0.f, 0.f, 0.f, 0.f);
    #pragma unroll
    for (int r = 0; r < 16; r++) {
        float4 v = *(const float4*)&src[(r0 + r) * 128 + c4];
        s4.x += v.x * v.x; s4.y += v.y * v.y;
        s4.z += v.z * v.z; s4.w += v.w * v.w;
        rbuf[2 * r]     = __float22bfloat162_rn(make_float2(v.x, v.y));
        rbuf[2 * r + 1] = __float22bfloat162_rn(make_float2(v.z, v.w));
    }
    __shared__ float4 sred[8][32];
    sred[w][lane] = s4;
    __syncthreads();
    float4 cs = make_float4(0.f, 0.f, 0.f, 0.f);
    #pragma unroll
    for (int gq = 0; gq < 8; gq++) {
        float4 a = sred[gq][lane];
        cs.x += a.x; cs.y += a.y; cs.z += a.z; cs.w += a.w;
    }
    float4 inv = make_float4(1.f / fmaxf(sqrtf(cs.x), 1e-12f),
                             1.f / fmaxf(sqrtf(cs.y), 1e-12f),
                             1.f / fmaxf(sqrtf(cs.z), 1e-12f),
                             1.f / fmaxf(sqrtf(cs.w), 1e-12f));
    float t = cs.x * inv.x * inv.x + cs.y * inv.y * inv.y
            + cs.z * inv.z * inv.z + cs.w * inv.w * inv.w;
    #pragma unroll
    for (int off = 16; off > 0; off >>= 1) t += __shfl_xor_sync(0xFFFFFFFF, t, off);
    const float finv = 1.f / fmaxf(sqrtf(t), 1e-8f);
    const float4 scl = make_float4(inv.x * finv * FP8_SCALE, inv.y * finv * FP8_SCALE,
                                   inv.z * finv * FP8_SCALE, inv.w * finv * FP8_SCALE);

    uint32_t* dst = (uint32_t*)(g_rn + (size_t)b * DFLAT);
    #pragma unroll
    for (int r = 0; r < 16; r++) {
        float2 lo = __bfloat1622float2(rbuf[2 * r]);
        float2 hi = __bfloat1622float2(rbuf[2 * r + 1]);
        uint32_t plo = f2_e4m3x2(lo.y * scl.y, lo.x * scl.x);
        uint32_t phi = f2_e4m3x2(hi.y * scl.w, hi.x * scl.z);
        dst[((r0 + r) * 128 + c4) >> 2] = (phi << 16) | plo;
    }
}

// ---------------- kernel 2: symmetric FP8 (f16-acc) GEMM, 3 CTAs/SM ----------------
#define BK       128
#define KSTEPS   (DFLAT / BK)          // 128
#define A_B      (128 * 128)           // 16 KB
#define B_B      (64 * 128)            // 8 KB
#define STAGE_B  (A_B + B_B)           // 24 KB
#define NSTAGE   3
#define GSMEM    (NSTAGE * STAGE_B)    // 72 KB -> 3 CTAs/SM (with <=85 regs)

__global__ void __launch_bounds__(256, 3) gemm_kernel(float* __restrict__ out) {
    extern __shared__ char sm[];
    const uint32_t sbase = smem_u32(sm);
    const int tid = threadIdx.x;
    const int warp = tid >> 5, lane = tid & 31;
    const int wm = warp >> 1, wn = warp & 1;
    const int g = lane >> 2, tig = lane & 3;

    int t = blockIdx.x >> 1, bm = 0;
    const int half = blockIdx.x & 1;
    while (t >= NBLK - bm) { t -= NBLK - bm; bm++; }
    const int bn = bm + t;
    const bool diag  = (bn == bm);
    const bool ptile = (bn - bm == 8);

    const uint8_t* gA = g_rn + (size_t)(bm * 128) * DFLAT;
    const uint8_t* gB = g_rn + (size_t)(bn * 128 + half * 64) * DFLAT;

    // ---- loop-invariant loader addresses (per-thread) ----
    // A chunks: c = tid + i*256, i=0..3 (c in [0,1024)); B chunks: i=4,5 (c2 = tid + (i-4)*256)
    uint32_t aOff[4]; const uint8_t* aPtr[4];
    #pragma unroll
    for (int i = 0; i < 4; i++) {
        int c = tid + i * 256;
        int row = c >> 3, cb = (c & 7) * 16;
        aOff[i] = row * 128 + (cb ^ ((row & 7) << 4));
        aPtr[i] = gA + (size_t)row * DFLAT + cb;
    }
    uint32_t bOff[2]; const uint8_t* bPtr[2];
    #pragma unroll
    for (int i = 0; i < 2; i++) {
        int c2 = tid + i * 256;
        int row = c2 >> 3, cb = (c2 & 7) * 16;
        bOff[i] = A_B + row * 128 + (cb ^ ((row & 7) << 4));
        bPtr[i] = gB + (size_t)row * DFLAT + cb;
    }

    uint32_t acc[2][4][2];
    #pragma unroll
    for (int mt = 0; mt < 2; mt++)
        #pragma unroll
        for (int nt = 0; nt < 4; nt++)
            acc[mt][nt][0] = acc[mt][nt][1] = 0u;

    auto load_stage = [&](int s) {
        const uint32_t base = sbase + (s % NSTAGE) * STAGE_B;
        const int k0 = s * BK;
        #pragma unroll
        for (int i = 0; i < 4; i++) cpasync16(base + aOff[i], aPtr[i] + k0);
        #pragma unroll
        for (int i = 0; i < 2; i++) cpasync16(base + bOff[i], bPtr[i] + k0);
    };

    load_stage(0); CP_COMMIT();
    load_stage(1); CP_COMMIT();

    const int lrow = lane & 15;
    const int hi   = (lane >> 4) * 16;
    uint32_t aBase[2], aXr[2], bBase[2], bXr[2];
    #pragma unroll
    for (int mt = 0; mt < 2; mt++) {
        int r = wm * 32 + mt * 16 + lrow;
        aBase[mt] = r * 128;  aXr[mt] = (r & 7) << 4;
    }
    #pragma unroll
    for (int p = 0; p < 2; p++) {
        int r = wn * 32 + p * 16 + lrow;
        bBase[p] = A_B + r * 128;  bXr[p] = (r & 7) << 4;
    }

    // 3-buffer ring, prefetch distance 2, single barrier per step:
    // at step s the barrier proves buf[(s-1)%3] is consumed -> free for s+2.
    for (int s = 0; s < KSTEPS; s++) {
        CP_WAIT(1);
        __syncthreads();
        if (s + 2 < KSTEPS) load_stage(s + 2);
        CP_COMMIT();
        const uint32_t stg = sbase + (s % NSTAGE) * STAGE_B;

        #pragma unroll
        for (int ks = 0; ks < 4; ks++) {
            const int kb = ks * 32 + hi;
            uint32_t a0[4], a1[4], bb[2][4];
            LDSM4(a0[0], a0[1], a0[2], a0[3], stg + aBase[0] + (kb ^ aXr[0]));
            LDSM4(a1[0], a1[1], a1[2], a1[3], stg + aBase[1] + (kb ^ aXr[1]));
            LDSM4(bb[0][0], bb[0][1], bb[0][2], bb[0][3], stg + bBase[0] + (kb ^ bXr[0]));
            LDSM4(bb[1][0], bb[1][1], bb[1][2], bb[1][3], stg + bBase[1] + (kb ^ bXr[1]));
            #pragma unroll
            for (int nt = 0; nt < 4; nt++) {
                uint32_t b0 = bb[nt >> 1][nt & 1];
                uint32_t b1 = bb[nt >> 1][(nt & 1) + 2];
                mma16832h(acc[0][nt], a0, b0, b1);
                mma16832h(acc[1][nt], a1, b0, b1);
            }
        }
    }

    // ---- fused epilogue ----
    float rowp[2][2] = {{0.f, 0.f}, {0.f, 0.f}};
    float colp[4][2];
    #pragma unroll
    for (int nt = 0; nt < 4; nt++) colp[nt][0] = colp[nt][1] = 0.f;

    #pragma unroll
    for (int mt = 0; mt < 2; mt++) {
        const int rl = wm * 32 + mt * 16 + g;
        #pragma unroll
        for (int nt = 0; nt < 4; nt++) {
            const int cg = half * 64 + wn * 32 + nt * 8 + tig * 2;
            float2 f01 = __half22float2(*(const __half2*)&acc[mt][nt][0]);
            float2 f23 = __half22float2(*(const __half2*)&acc[mt][nt][1]);
            float v0 = f01.x * INV_ACC, v1 = f01.y * INV_ACC;
            float v2 = f23.x * INV_ACC, v3 = f23.y * INV_ACC;
            float e0 = __expf(2.f * v0), e1 = __expf(2.f * v1);
            float e2 = __expf(2.f * v2), e3 = __expf(2.f * v3);
            if (diag) {
                if (rl == cg)         e0 = 0.f;
                if (rl == cg + 1)     e1 = 0.f;
                if (rl + 8 == cg)     e2 = 0.f;
                if (rl + 8 == cg + 1) e3 = 0.f;
            }
            if (ptile) {
                int gr = bm * 128 + rl;
                if (rl == cg)         { g_pos[gr]     = v0; g_pos[gr + BATCH]     = v0; }
                if (rl == cg + 1)     { g_pos[gr]     = v1; g_pos[gr + BATCH]     = v1; }
                if (rl + 8 == cg)     { g_pos[gr + 8] = v2; g_pos[gr + 8 + BATCH] = v2; }
                if (rl + 8 == cg + 1) { g_pos[gr + 8] = v3; g_pos[gr + 8 + BATCH] = v3; }
            }
            rowp[mt][0] += e0 + e1;
            rowp[mt][1] += e2 + e3;
            colp[nt][0] += e0 + e2;
            colp[nt][1] += e1 + e3;
        }
    }

    #pragma unroll
    for (int mt = 0; mt < 2; mt++)
        #pragma unroll
        for (int h = 0; h < 2; h++) {
            float v = rowp[mt][h];
            v += __shfl_xor_sync(0xFFFFFFFF, v, 1);
            v += __shfl_xor_sync(0xFFFFFFFF, v, 2);
            if (tig == 0)
                atomicAdd(&g_row[bm * 128 + wm * 32 + mt * 16 + g + h * 8], v);
        }

    if (!diag) {
        #pragma unroll
        for (int nt = 0; nt < 4; nt++)
            #pragma unroll
            for (int q = 0; q < 2; q++) {
                float v = colp[nt][q];
                v += __shfl_xor_sync(0xFFFFFFFF, v, 4);
                v += __shfl_xor_sync(0xFFFFFFFF, v, 8);
                v += __shfl_xor_sync(0xFFFFFFFF, v, 16);
                if (g == 0)
                    atomicAdd(&g_row[bn * 128 + half * 64 + wn * 32 + nt * 8 + tig * 2 + q], v);
            }
    }

    // ---- last-CTA ticket: inline final reduction ----
    __threadfence();
    __syncthreads();
    __shared__ int is_last;
    if (tid == 0) is_last = (atomicAdd(&g_done, 1) == NCTA - 1) ? 1 : 0;
    __syncthreads();
    if (is_last) {
        __threadfence();
        float s = 0.f;
        #pragma unroll
        for (int k = 0; k < 8; k++) {
            int i = tid + k * 256;
            s += logf(g_row[i]) - 2.f * g_pos[i];
        }
        float* red = (float*)sm;
        red[tid] = s;
        __syncthreads();
        for (int off = 128; off > 0; off >>= 1) {
            if (tid < off) red[tid] += red[tid + off];
            __syncthreads();
        }
        if (tid == 0) {
            out[0] = red[0] / (float)TWO_B;
            g_done = 0;
            __threadfence();
        }
    }
}

// ---------------- launch ----------------
extern "C" void kernel_launch(void* const* d_in, const int* in_sizes, int n_in,
                              void* d_out, int out_size) {
    const float* ei = (const float*)d_in[0];
    const float* ej = (const float*)d_in[1];
    float* out = (float*)d_out;

    cudaFuncSetAttribute(gemm_kernel, cudaFuncAttributeMaxDynamicSharedMemorySize, GSMEM);

    nrm_kernel<<<TWO_B, 256>>>(ei, ej);
    gemm_kernel<<<NCTA, 256, GSMEM>>>(out);
}

// round 11
// speedup vs baseline: 1.0279x; 1.0279x over previous
#include <cuda_runtime.h>
#include <cuda_bf16.h>
#include <cuda_fp16.h>
#include <cstdint>

#define BATCH   1024
#define TWO_B   2048
#define DFLAT   16384
#define NBLK    16
#define FP8_SCALE 128.f
#define INV_ACC   (1.f / 16384.f)

// ---------------- scratch ----------------
__device__ uint8_t g_rn[(size_t)TWO_B * DFLAT];   // 32 MB e4m3 (L2-resident)
__device__ float   g_row[TWO_B];
__device__ float   g_pos[TWO_B];

// ---------------- helpers ----------------
__device__ __forceinline__ uint32_t smem_u32(const void* p) {
    return (uint32_t)__cvta_generic_to_shared(p);
}
__device__ __forceinline__ void cpasync16(uint32_t s, const void* g) {
    asm volatile("cp.async.ca.shared.global [%0], [%1], 16;\n" :: "r"(s), "l"(g));
}
#define CP_COMMIT() asm volatile("cp.async.commit_group;\n")
#define CP_WAIT(N)  asm volatile("cp.async.wait_group %0;\n" :: "n"(N))

#define LDSM4(r0, r1, r2, r3, a) \
    asm volatile("ldmatrix.sync.aligned.m8n8.x4.shared.b16 {%0,%1,%2,%3}, [%4];" \
                 : "=r"(r0), "=r"(r1), "=r"(r2), "=r"(r3) : "r"(a))

// fp8 e4m3 mma with f16 accumulators (fastest register path measured on sm_103a)
__device__ __forceinline__ void mma16832h(uint32_t* c, const uint32_t* a, uint32_t b0, uint32_t b1) {
    asm volatile(
        "mma.sync.aligned.m16n8k32.row.col.f16.e4m3.e4m3.f16 "
        "{%0,%1}, {%2,%3,%4,%5}, {%6,%7}, {%0,%1};\n"
        : "+r"(c[0]), "+r"(c[1])
        : "r"(a[0]), "r"(a[1]), "r"(a[2]), "r"(a[3]), "r"(b0), "r"(b1));
}

__device__ __forceinline__ uint32_t f2_e4m3x2(float hi, float lo) {
    uint16_t r;
    asm volatile("cvt.rn.satfinite.e4m3x2.f32 %0, %1, %2;" : "=h"(r) : "f"(hi), "f"(lo));
    return (uint32_t)r;
}

// ---------------- kernel 1: fused double normalization -> scaled e4m3 (R6 proven) ----------------
__global__ void __launch_bounds__(128) nrm_kernel(const float* __restrict__ ei,
                                                  const float* __restrict__ ej) {
    const int b = blockIdx.x;
    const float* src = (b < BATCH) ? (ei + (size_t)b * DFLAT)
                                   : (ej + (size_t)(b - BATCH) * DFLAT);
    const int tid = threadIdx.x;
    const int w = tid >> 5, lane = tid & 31;
    const int c4 = lane * 4;
    const int r0 = w * 32;
    if (tid == 0) g_row[b] = 0.f;

    __nv_bfloat162 rbuf[64];
    float4 s4 = make_float4(0.f, 0.f, 0.f, 0.f);
    #pragma unroll
    for (int r = 0; r < 32; r++) {
        float4 v = *(const float4*)&src[(r0 + r) * 128 + c4];
        s4.x += v.x * v.x; s4.y += v.y * v.y;
        s4.z += v.z * v.z; s4.w += v.w * v.w;
        rbuf[2 * r]     = __float22bfloat162_rn(make_float2(v.x, v.y));
        rbuf[2 * r + 1] = __float22bfloat162_rn(make_float2(v.z, v.w));
    }
    __shared__ float4 sred[4][32];
    sred[w][lane] = s4;
    __syncthreads();
    float4 cs;
    {
        float4 a = sred[0][lane], bb = sred[1][lane], c = sred[2][lane], d = sred[3][lane];
        cs = make_float4(a.x + bb.x + c.x + d.x, a.y + bb.y + c.y + d.y,
                         a.z + bb.z + c.z + d.z, a.w + bb.w + c.w + d.w);
    }
    float4 inv = make_float4(1.f / fmaxf(sqrtf(cs.x), 1e-12f),
                             1.f / fmaxf(sqrtf(cs.y), 1e-12f),
                             1.f / fmaxf(sqrtf(cs.z), 1e-12f),
                             1.f / fmaxf(sqrtf(cs.w), 1e-12f));
    float t = cs.x * inv.x * inv.x + cs.y * inv.y * inv.y
            + cs.z * inv.z * inv.z + cs.w * inv.w * inv.w;
    #pragma unroll
    for (int off = 16; off > 0; off >>= 1) t += __shfl_xor_sync(0xFFFFFFFF, t, off);
    const float finv = 1.f / fmaxf(sqrtf(t), 1e-8f);
    const float4 scl = make_float4(inv.x * finv * FP8_SCALE, inv.y * finv * FP8_SCALE,
                                   inv.z * finv * FP8_SCALE, inv.w * finv * FP8_SCALE);

    uint32_t* dst = (uint32_t*)(g_rn + (size_t)b * DFLAT);
    #pragma unroll
    for (int r = 0; r < 32; r++) {
        float2 lo = __bfloat1622float2(rbuf[2 * r]);
        float2 hi = __bfloat1622float2(rbuf[2 * r + 1]);
        uint32_t plo = f2_e4m3x2(lo.y * scl.y, lo.x * scl.x);
        uint32_t phi = f2_e4m3x2(hi.y * scl.w, hi.x * scl.z);
        dst[((r0 + r) * 128 + c4) >> 2] = (phi << 16) | plo;
    }
}

// ---------------- kernel 2: symmetric FP8 (f16-acc) GEMM + fused exp/row-reduce epilogue ----------------
// R6 structure: 272 CTAs (136 pairs x 2 halves, tile 128x64), BK=128 bytes,
// 4-stage cp.async ring (single barrier/step), 8 warps (4x2), warp tile 32x32.
// R10 delta: all 16 LDSM addresses precomputed (loop-invariant) -> 1 IADD per LDSM.
#define BK       128
#define KSTEPS   (DFLAT / BK)          // 128
#define A_B      (128 * 128)           // 16 KB
#define B_B      (64 * 128)            // 8 KB
#define STAGE_B  (A_B + B_B)           // 24 KB
#define NSTAGE   4
#define GSMEM    (NSTAGE * STAGE_B)    // 96 KB -> 2 CTAs/SM

__global__ void __launch_bounds__(256, 2) gemm_kernel() {
    extern __shared__ char sm[];
    const uint32_t sbase = smem_u32(sm);
    const int tid = threadIdx.x;
    const int warp = tid >> 5, lane = tid & 31;
    const int wm = warp >> 1, wn = warp & 1;
    const int g = lane >> 2, tig = lane & 3;

    int t = blockIdx.x >> 1, bm = 0;
    const int half = blockIdx.x & 1;
    while (t >= NBLK - bm) { t -= NBLK - bm; bm++; }
    const int bn = bm + t;
    const bool diag  = (bn == bm);
    const bool ptile = (bn - bm == 8);

    const uint8_t* gA = g_rn + (size_t)(bm * 128) * DFLAT;
    const uint8_t* gB = g_rn + (size_t)(bn * 128 + half * 64) * DFLAT;

    uint32_t acc[2][4][2];
    #pragma unroll
    for (int mt = 0; mt < 2; mt++)
        #pragma unroll
        for (int nt = 0; nt < 4; nt++)
            acc[mt][nt][0] = acc[mt][nt][1] = 0u;

    auto load_stage = [&](int s, int buf) {
        const uint32_t base = sbase + buf * STAGE_B;
        const int k0 = s * BK;
        #pragma unroll
        for (int i = 0; i < 6; i++) {
            int c = tid + i * 256;
            bool isA = (c < 1024);
            int cc  = isA ? c : (c - 1024);
            int row = cc >> 3;
            int cb  = (cc & 7) * 16;
            uint32_t off = row * 128 + (cb ^ ((row & 7) << 4));
            const uint8_t* src = (isA ? gA : gB) + (size_t)row * DFLAT + k0 + cb;
            cpasync16(base + (isA ? 0 : A_B) + off, src);
        }
    };

    load_stage(0, 0); CP_COMMIT();
    load_stage(1, 1); CP_COMMIT();
    load_stage(2, 2); CP_COMMIT();

    // ---- precomputed per-lane LDSM addresses: [operand][ks], loop-invariant ----
    const int lrow = lane & 15;
    const int hi   = (lane >> 4) * 16;
    uint32_t aAd[2][4], bAd[2][4];
    #pragma unroll
    for (int mt = 0; mt < 2; mt++) {
        int r = wm * 32 + mt * 16 + lrow;
        uint32_t base = r * 128, xr = (r & 7) << 4;
        #pragma unroll
        for (int ks = 0; ks < 4; ks++)
            aAd[mt][ks] = base + ((ks * 32 + hi) ^ xr);
    }
    #pragma unroll
    for (int p = 0; p < 2; p++) {
        int r = wn * 32 + p * 16 + lrow;
        uint32_t base = A_B + r * 128, xr = (r & 7) << 4;
        #pragma unroll
        for (int ks = 0; ks < 4; ks++)
            bAd[p][ks] = base + ((ks * 32 + hi) ^ xr);
    }

    for (int s = 0; s < KSTEPS; s++) {
        CP_WAIT(2);
        __syncthreads();                      // single barrier per step (4-stage ring)
        const uint32_t stg = sbase + (s & 3) * STAGE_B;

        #pragma unroll
        for (int ks = 0; ks < 4; ks++) {
            uint32_t a0[4], a1[4], bb[2][4];
            LDSM4(a0[0], a0[1], a0[2], a0[3], stg + aAd[0][ks]);
            LDSM4(a1[0], a1[1], a1[2], a1[3], stg + aAd[1][ks]);
            LDSM4(bb[0][0], bb[0][1], bb[0][2], bb[0][3], stg + bAd[0][ks]);
            LDSM4(bb[1][0], bb[1][1], bb[1][2], bb[1][3], stg + bAd[1][ks]);
            #pragma unroll
            for (int nt = 0; nt < 4; nt++) {
                uint32_t b0 = bb[nt >> 1][nt & 1];
                uint32_t b1 = bb[nt >> 1][(nt & 1) + 2];
                mma16832h(acc[0][nt], a0, b0, b1);
                mma16832h(acc[1][nt], a1, b0, b1);
            }
        }
        if (s + 3 < KSTEPS) load_stage(s + 3, (s + 3) & 3);
        CP_COMMIT();
    }

    // fused epilogue: promote f16 accs, v = acc/S^2; e = exp(2v); rows + cols
    float rowp[2][2] = {{0.f, 0.f}, {0.f, 0.f}};
    float colp[4][2];
    #pragma unroll
    for (int nt = 0; nt < 4; nt++) colp[nt][0] = colp[nt][1] = 0.f;

    #pragma unroll
    for (int mt = 0; mt < 2; mt++) {
        const int rl = wm * 32 + mt * 16 + g;
        #pragma unroll
        for (int nt = 0; nt < 4; nt++) {
            const int cg = half * 64 + wn * 32 + nt * 8 + tig * 2;
            float2 f01 = __half22float2(*(const __half2*)&acc[mt][nt][0]);
            float2 f23 = __half22float2(*(const __half2*)&acc[mt][nt][1]);
            float v0 = f01.x * INV_ACC, v1 = f01.y * INV_ACC;
            float v2 = f23.x * INV_ACC, v3 = f23.y * INV_ACC;
            float e0 = __expf(2.f * v0), e1 = __expf(2.f * v1);
            float e2 = __expf(2.f * v2), e3 = __expf(2.f * v3);
            if (diag) {
                if (rl == cg)         e0 = 0.f;
                if (rl == cg + 1)     e1 = 0.f;
                if (rl + 8 == cg)     e2 = 0.f;
                if (rl + 8 == cg + 1) e3 = 0.f;
            }
            if (ptile) {
                int gr = bm * 128 + rl;
                if (rl == cg)         { g_pos[gr]     = v0; g_pos[gr + BATCH]     = v0; }
                if (rl == cg + 1)     { g_pos[gr]     = v1; g_pos[gr + BATCH]     = v1; }
                if (rl + 8 == cg)     { g_pos[gr + 8] = v2; g_pos[gr + 8 + BATCH] = v2; }
                if (rl + 8 == cg + 1) { g_pos[gr + 8] = v3; g_pos[gr + 8 + BATCH] = v3; }
            }
            rowp[mt][0] += e0 + e1;
            rowp[mt][1] += e2 + e3;
            colp[nt][0] += e0 + e2;
            colp[nt][1] += e1 + e3;
        }
    }

    #pragma unroll
    for (int mt = 0; mt < 2; mt++)
        #pragma unroll
        for (int h = 0; h < 2; h++) {
            float v = rowp[mt][h];
            v += __shfl_xor_sync(0xFFFFFFFF, v, 1);
            v += __shfl_xor_sync(0xFFFFFFFF, v, 2);
            if (tig == 0)
                atomicAdd(&g_row[bm * 128 + wm * 32 + mt * 16 + g + h * 8], v);
        }

    if (!diag) {
        #pragma unroll
        for (int nt = 0; nt < 4; nt++)
            #pragma unroll
            for (int q = 0; q < 2; q++) {
                float v = colp[nt][q];
                v += __shfl_xor_sync(0xFFFFFFFF, v, 4);
                v += __shfl_xor_sync(0xFFFFFFFF, v, 8);
                v += __shfl_xor_sync(0xFFFFFFFF, v, 16);
                if (g == 0)
                    atomicAdd(&g_row[bn * 128 + half * 64 + wn * 32 + nt * 8 + tig * 2 + q], v);
            }
    }
}

// ---------------- kernel 3: final scalar ----------------
__global__ void fin_kernel(float* __restrict__ out) {
    float s = 0.f;
    for (int i = threadIdx.x; i < TWO_B; i += 256)
        s += logf(g_row[i]) - 2.f * g_pos[i];
    __shared__ float red[256];
    red[threadIdx.x] = s;
    __syncthreads();
    for (int off = 128; off > 0; off >>= 1) {
        if (threadIdx.x < off) red[threadIdx.x] += red[threadIdx.x + off];
        __syncthreads();
    }
    if (threadIdx.x == 0) out[0] = red[0] / (float)TWO_B;
}

// ---------------- launch ----------------
extern "C" void kernel_launch(void* const* d_in, const int* in_sizes, int n_in,
                              void* d_out, int out_size) {
    const float* ei = (const float*)d_in[0];
    const float* ej = (const float*)d_in[1];
    float* out = (float*)d_out;

    cudaFuncSetAttribute(gemm_kernel, cudaFuncAttributeMaxDynamicSharedMemorySize, GSMEM);

    nrm_kernel<<<TWO_B, 128>>>(ei, ej);
    gemm_kernel<<<272, 256, GSMEM>>>();
    fin_kernel<<<1, 256>>>(out);
}

// round 12
// speedup vs baseline: 1.1584x; 1.1269x over previous
#include <cuda_runtime.h>
#include <cuda_bf16.h>
#include <cuda_fp16.h>
#include <cstdint>

#define BATCH   1024
#define TWO_B   2048
#define DFLAT   16384
#define NBLK    16
#define FP8_SCALE 128.f
#define INV_ACC   (1.f / 16384.f)

// ---------------- scratch ----------------
__device__ uint8_t g_rn[(size_t)TWO_B * DFLAT];   // 32 MB e4m3 (L2-resident)
__device__ float   g_row[TWO_B];
__device__ float   g_pos[TWO_B];

// ---------------- helpers ----------------
__device__ __forceinline__ uint32_t smem_u32(const void* p) {
    return (uint32_t)__cvta_generic_to_shared(p);
}
__device__ __forceinline__ void cpasync16(uint32_t s, const void* g) {
    asm volatile("cp.async.ca.shared.global [%0], [%1], 16;\n" :: "r"(s), "l"(g));
}
#define CP_COMMIT() asm volatile("cp.async.commit_group;\n")
#define CP_WAIT(N)  asm volatile("cp.async.wait_group %0;\n" :: "n"(N))

#define LDSM4(r0, r1, r2, r3, a) \
    asm volatile("ldmatrix.sync.aligned.m8n8.x4.shared.b16 {%0,%1,%2,%3}, [%4];" \
                 : "=r"(r0), "=r"(r1), "=r"(r2), "=r"(r3) : "r"(a))

// fp8 e4m3 mma with f16 accumulators (fastest register path measured on sm_103a)
__device__ __forceinline__ void mma16832h(uint32_t* c, const uint32_t* a, uint32_t b0, uint32_t b1) {
    asm volatile(
        "mma.sync.aligned.m16n8k32.row.col.f16.e4m3.e4m3.f16 "
        "{%0,%1}, {%2,%3,%4,%5}, {%6,%7}, {%0,%1};\n"
        : "+r"(c[0]), "+r"(c[1])
        : "r"(a[0]), "r"(a[1]), "r"(a[2]), "r"(a[3]), "r"(b0), "r"(b1));
}

__device__ __forceinline__ uint32_t f2_e4m3x2(float hi, float lo) {
    uint16_t r;
    asm volatile("cvt.rn.satfinite.e4m3x2.f32 %0, %1, %2;" : "=h"(r) : "f"(hi), "f"(lo));
    return (uint32_t)r;
}

// ---------------- kernel 1: fused double normalization -> scaled e4m3 (R6 proven) ----------------
__global__ void __launch_bounds__(128) nrm_kernel(const float* __restrict__ ei,
                                                  const float* __restrict__ ej) {
    const int b = blockIdx.x;
    const float* src = (b < BATCH) ? (ei + (size_t)b * DFLAT)
                                   : (ej + (size_t)(b - BATCH) * DFLAT);
    const int tid = threadIdx.x;
    const int w = tid >> 5, lane = tid & 31;
    const int c4 = lane * 4;
    const int r0 = w * 32;
    if (tid == 0) g_row[b] = 0.f;

    __nv_bfloat162 rbuf[64];
    float4 s4 = make_float4(0.f, 0.f, 0.f, 0.f);
    #pragma unroll
    for (int r = 0; r < 32; r++) {
        float4 v = *(const float4*)&src[(r0 + r) * 128 + c4];
        s4.x += v.x * v.x; s4.y += v.y * v.y;
        s4.z += v.z * v.z; s4.w += v.w * v.w;
        rbuf[2 * r]     = __float22bfloat162_rn(make_float2(v.x, v.y));
        rbuf[2 * r + 1] = __float22bfloat162_rn(make_float2(v.z, v.w));
    }
    __shared__ float4 sred[4][32];
    sred[w][lane] = s4;
    __syncthreads();
    float4 cs;
    {
        float4 a = sred[0][lane], bb = sred[1][lane], c = sred[2][lane], d = sred[3][lane];
        cs = make_float4(a.x + bb.x + c.x + d.x, a.y + bb.y + c.y + d.y,
                         a.z + bb.z + c.z + d.z, a.w + bb.w + c.w + d.w);
    }
    float4 inv = make_float4(1.f / fmaxf(sqrtf(cs.x), 1e-12f),
                             1.f / fmaxf(sqrtf(cs.y), 1e-12f),
                             1.f / fmaxf(sqrtf(cs.z), 1e-12f),
                             1.f / fmaxf(sqrtf(cs.w), 1e-12f));
    float t = cs.x * inv.x * inv.x + cs.y * inv.y * inv.y
            + cs.z * inv.z * inv.z + cs.w * inv.w * inv.w;
    #pragma unroll
    for (int off = 16; off > 0; off >>= 1) t += __shfl_xor_sync(0xFFFFFFFF, t, off);
    const float finv = 1.f / fmaxf(sqrtf(t), 1e-8f);
    const float4 scl = make_float4(inv.x * finv * FP8_SCALE, inv.y * finv * FP8_SCALE,
                                   inv.z * finv * FP8_SCALE, inv.w * finv * FP8_SCALE);

    uint32_t* dst = (uint32_t*)(g_rn + (size_t)b * DFLAT);
    #pragma unroll
    for (int r = 0; r < 32; r++) {
        float2 lo = __bfloat1622float2(rbuf[2 * r]);
        float2 hi = __bfloat1622float2(rbuf[2 * r + 1]);
        uint32_t plo = f2_e4m3x2(lo.y * scl.y, lo.x * scl.x);
        uint32_t phi = f2_e4m3x2(hi.y * scl.w, hi.x * scl.z);
        dst[((r0 + r) * 128 + c4) >> 2] = (phi << 16) | plo;
    }
}

// ---------------- kernel 2: symmetric FP8 (f16-acc) GEMM + fused exp/row-reduce epilogue ----------------
// R6 structure: 272 CTAs (136 pairs x 2 halves, tile 128x64), BK=128 bytes,
// 4-stage cp.async ring (single barrier/step), 8 warps (4x2), warp tile 32x32.
// R11 delta: register double-buffered ldmatrix fragments (prefetch ks+1 before ks's MMAs).
#define BK       128
#define KSTEPS   (DFLAT / BK)          // 128
#define A_B      (128 * 128)           // 16 KB
#define B_B      (64 * 128)            // 8 KB
#define STAGE_B  (A_B + B_B)           // 24 KB
#define NSTAGE   4
#define GSMEM    (NSTAGE * STAGE_B)    // 96 KB -> 2 CTAs/SM

__global__ void __launch_bounds__(256, 2) gemm_kernel() {
    extern __shared__ char sm[];
    const uint32_t sbase = smem_u32(sm);
    const int tid = threadIdx.x;
    const int warp = tid >> 5, lane = tid & 31;
    const int wm = warp >> 1, wn = warp & 1;
    const int g = lane >> 2, tig = lane & 3;

    int t = blockIdx.x >> 1, bm = 0;
    const int half = blockIdx.x & 1;
    while (t >= NBLK - bm) { t -= NBLK - bm; bm++; }
    const int bn = bm + t;
    const bool diag  = (bn == bm);
    const bool ptile = (bn - bm == 8);

    const uint8_t* gA = g_rn + (size_t)(bm * 128) * DFLAT;
    const uint8_t* gB = g_rn + (size_t)(bn * 128 + half * 64) * DFLAT;

    uint32_t acc[2][4][2];
    #pragma unroll
    for (int mt = 0; mt < 2; mt++)
        #pragma unroll
        for (int nt = 0; nt < 4; nt++)
            acc[mt][nt][0] = acc[mt][nt][1] = 0u;

    auto load_stage = [&](int s, int buf) {
        const uint32_t base = sbase + buf * STAGE_B;
        const int k0 = s * BK;
        #pragma unroll
        for (int i = 0; i < 6; i++) {
            int c = tid + i * 256;
            bool isA = (c < 1024);
            int cc  = isA ? c : (c - 1024);
            int row = cc >> 3;
            int cb  = (cc & 7) * 16;
            uint32_t off = row * 128 + (cb ^ ((row & 7) << 4));
            const uint8_t* src = (isA ? gA : gB) + (size_t)row * DFLAT + k0 + cb;
            cpasync16(base + (isA ? 0 : A_B) + off, src);
        }
    };

    load_stage(0, 0); CP_COMMIT();
    load_stage(1, 1); CP_COMMIT();
    load_stage(2, 2); CP_COMMIT();

    const int lrow = lane & 15;
    const int hi   = (lane >> 4) * 16;
    uint32_t aBase[2], aXr[2], bBase[2], bXr[2];
    #pragma unroll
    for (int mt = 0; mt < 2; mt++) {
        int r = wm * 32 + mt * 16 + lrow;
        aBase[mt] = r * 128;  aXr[mt] = (r & 7) << 4;
    }
    #pragma unroll
    for (int p = 0; p < 2; p++) {
        int r = wn * 32 + p * 16 + lrow;
        bBase[p] = A_B + r * 128;  bXr[p] = (r & 7) << 4;
    }

    for (int s = 0; s < KSTEPS; s++) {
        CP_WAIT(2);
        __syncthreads();                      // single barrier per step (4-stage ring)
        const uint32_t stg = sbase + (s & 3) * STAGE_B;

        // register double-buffered fragments: [operand][buf][4]
        uint32_t fA0[2][4], fA1[2][4], fB0[2][4], fB1[2][4];
        LDSM4(fA0[0][0], fA0[0][1], fA0[0][2], fA0[0][3], stg + aBase[0] + (hi ^ aXr[0]));
        LDSM4(fA1[0][0], fA1[0][1], fA1[0][2], fA1[0][3], stg + aBase[1] + (hi ^ aXr[1]));
        LDSM4(fB0[0][0], fB0[0][1], fB0[0][2], fB0[0][3], stg + bBase[0] + (hi ^ bXr[0]));
        LDSM4(fB1[0][0], fB1[0][1], fB1[0][2], fB1[0][3], stg + bBase[1] + (hi ^ bXr[1]));

        #pragma unroll
        for (int ks = 0; ks < 4; ks++) {
            const int cur = ks & 1, nxt = cur ^ 1;
            if (ks < 3) {                     // prefetch ks+1 fragments before MMAs
                const int kb = (ks + 1) * 32 + hi;
                LDSM4(fA0[nxt][0], fA0[nxt][1], fA0[nxt][2], fA0[nxt][3], stg + aBase[0] + (kb ^ aXr[0]));
                LDSM4(fA1[nxt][0], fA1[nxt][1], fA1[nxt][2], fA1[nxt][3], stg + aBase[1] + (kb ^ aXr[1]));
                LDSM4(fB0[nxt][0], fB0[nxt][1], fB0[nxt][2], fB0[nxt][3], stg + bBase[0] + (kb ^ bXr[0]));
                LDSM4(fB1[nxt][0], fB1[nxt][1], fB1[nxt][2], fB1[nxt][3], stg + bBase[1] + (kb ^ bXr[1]));
            }
            #pragma unroll
            for (int nt = 0; nt < 4; nt++) {
                uint32_t b0 = (nt < 2) ? fB0[cur][nt & 1]       : fB1[cur][nt & 1];
                uint32_t b1 = (nt < 2) ? fB0[cur][(nt & 1) + 2] : fB1[cur][(nt & 1) + 2];
                mma16832h(acc[0][nt], fA0[cur], b0, b1);
                mma16832h(acc[1][nt], fA1[cur], b0, b1);
            }
        }
        if (s + 3 < KSTEPS) load_stage(s + 3, (s + 3) & 3);
        CP_COMMIT();
    }

    // fused epilogue: promote f16 accs, v = acc/S^2; e = exp(2v); rows + cols
    float rowp[2][2] = {{0.f, 0.f}, {0.f, 0.f}};
    float colp[4][2];
    #pragma unroll
    for (int nt = 0; nt < 4; nt++) colp[nt][0] = colp[nt][1] = 0.f;

    #pragma unroll
    for (int mt = 0; mt < 2; mt++) {
        const int rl = wm * 32 + mt * 16 + g;
        #pragma unroll
        for (int nt = 0; nt < 4; nt++) {
            const int cg = half * 64 + wn * 32 + nt * 8 + tig * 2;
            float2 f01 = __half22float2(*(const __half2*)&acc[mt][nt][0]);
            float2 f23 = __half22float2(*(const __half2*)&acc[mt][nt][1]);
            float v0 = f01.x * INV_ACC, v1 = f01.y * INV_ACC;
            float v2 = f23.x * INV_ACC, v3 = f23.y * INV_ACC;
            float e0 = __expf(2.f * v0), e1 = __expf(2.f * v1);
            float e2 = __expf(2.f * v2), e3 = __expf(2.f * v3);
            if (diag) {
                if (rl == cg)         e0 = 0.f;
                if (rl == cg + 1)     e1 = 0.f;
                if (rl + 8 == cg)     e2 = 0.f;
                if (rl + 8 == cg + 1) e3 = 0.f;
            }
            if (ptile) {
                int gr = bm * 128 + rl;
                if (rl == cg)         { g_pos[gr]     = v0; g_pos[gr + BATCH]     = v0; }
                if (rl == cg + 1)     { g_pos[gr]     = v1; g_pos[gr + BATCH]     = v1; }
                if (rl + 8 == cg)     { g_pos[gr + 8] = v2; g_pos[gr + 8 + BATCH] = v2; }
                if (rl + 8 == cg + 1) { g_pos[gr + 8] = v3; g_pos[gr + 8 + BATCH] = v3; }
            }
            rowp[mt][0] += e0 + e1;
            rowp[mt][1] += e2 + e3;
            colp[nt][0] += e0 + e2;
            colp[nt][1] += e1 + e3;
        }
    }

    #pragma unroll
    for (int mt = 0; mt < 2; mt++)
        #pragma unroll
        for (int h = 0; h < 2; h++) {
            float v = rowp[mt][h];
            v += __shfl_xor_sync(0xFFFFFFFF, v, 1);
            v += __shfl_xor_sync(0xFFFFFFFF, v, 2);
            if (tig == 0)
                atomicAdd(&g_row[bm * 128 + wm * 32 + mt * 16 + g + h * 8], v);
        }

    if (!diag) {
        #pragma unroll
        for (int nt = 0; nt < 4; nt++)
            #pragma unroll
            for (int q = 0; q < 2; q++) {
                float v = colp[nt][q];
                v += __shfl_xor_sync(0xFFFFFFFF, v, 4);
                v += __shfl_xor_sync(0xFFFFFFFF, v, 8);
                v += __shfl_xor_sync(0xFFFFFFFF, v, 16);
                if (g == 0)
                    atomicAdd(&g_row[bn * 128 + half * 64 + wn * 32 + nt * 8 + tig * 2 + q], v);
            }
    }
}

// ---------------- kernel 3: final scalar ----------------
__global__ void fin_kernel(float* __restrict__ out) {
    float s = 0.f;
    for (int i = threadIdx.x; i < TWO_B; i += 256)
        s += logf(g_row[i]) - 2.f * g_pos[i];
    __shared__ float red[256];
    red[threadIdx.x] = s;
    __syncthreads();
    for (int off = 128; off > 0; off >>= 1) {
        if (threadIdx.x < off) red[threadIdx.x] += red[threadIdx.x + off];
        __syncthreads();
    }
    if (threadIdx.x == 0) out[0] = red[0] / (float)TWO_B;
}

// ---------------- launch ----------------
extern "C" void kernel_launch(void* const* d_in, const int* in_sizes, int n_in,
                              void* d_out, int out_size) {
    const float* ei = (const float*)d_in[0];
    const float* ej = (const float*)d_in[1];
    float* out = (float*)d_out;

    cudaFuncSetAttribute(gemm_kernel, cudaFuncAttributeMaxDynamicSharedMemorySize, GSMEM);

    nrm_kernel<<<TWO_B, 128>>>(ei, ej);
    gemm_kernel<<<272, 256, GSMEM>>>();
    fin_kernel<<<1, 256>>>(out);
}

// round 13
// speedup vs baseline: 1.1799x; 1.0186x over previous
#include <cuda_runtime.h>
#include <cuda_bf16.h>
#include <cuda_fp16.h>
#include <cstdint>

#define BATCH   1024
#define TWO_B   2048
#define DFLAT   16384
#define NBLK    16
#define FP8_SCALE 128.f
#define INV_ACC   (1.f / 16384.f)

// ---------------- scratch ----------------
__device__ uint8_t g_rn[(size_t)TWO_B * DFLAT];   // 32 MB e4m3 (L2-resident)
__device__ float   g_row[TWO_B];
__device__ float   g_pos[TWO_B];

// ---------------- helpers ----------------
__device__ __forceinline__ uint32_t smem_u32(const void* p) {
    return (uint32_t)__cvta_generic_to_shared(p);
}
__device__ __forceinline__ void cpasync16(uint32_t s, const void* g) {
    asm volatile("cp.async.ca.shared.global [%0], [%1], 16;\n" :: "r"(s), "l"(g));
}
#define CP_COMMIT() asm volatile("cp.async.commit_group;\n")
#define CP_WAIT(N)  asm volatile("cp.async.wait_group %0;\n" :: "n"(N))

#define LDSM4(r0, r1, r2, r3, a) \
    asm volatile("ldmatrix.sync.aligned.m8n8.x4.shared.b16 {%0,%1,%2,%3}, [%4];" \
                 : "=r"(r0), "=r"(r1), "=r"(r2), "=r"(r3) : "r"(a))

// fp8 e4m3 mma with f16 accumulators (fastest register path measured on sm_103a)
__device__ __forceinline__ void mma16832h(uint32_t* c, const uint32_t* a, uint32_t b0, uint32_t b1) {
    asm volatile(
        "mma.sync.aligned.m16n8k32.row.col.f16.e4m3.e4m3.f16 "
        "{%0,%1}, {%2,%3,%4,%5}, {%6,%7}, {%0,%1};\n"
        : "+r"(c[0]), "+r"(c[1])
        : "r"(a[0]), "r"(a[1]), "r"(a[2]), "r"(a[3]), "r"(b0), "r"(b1));
}

__device__ __forceinline__ uint32_t f2_e4m3x2(float hi, float lo) {
    uint16_t r;
    asm volatile("cvt.rn.satfinite.e4m3x2.f32 %0, %1, %2;" : "=h"(r) : "f"(hi), "f"(lo));
    return (uint32_t)r;
}

// ---------------- kernel 1: fused double normalization -> scaled e4m3 (proven) ----------------
__global__ void __launch_bounds__(128) nrm_kernel(const float* __restrict__ ei,
                                                  const float* __restrict__ ej) {
    const int b = blockIdx.x;
    const float* src = (b < BATCH) ? (ei + (size_t)b * DFLAT)
                                   : (ej + (size_t)(b - BATCH) * DFLAT);
    const int tid = threadIdx.x;
    const int w = tid >> 5, lane = tid & 31;
    const int c4 = lane * 4;
    const int r0 = w * 32;
    if (tid == 0) g_row[b] = 0.f;

    __nv_bfloat162 rbuf[64];
    float4 s4 = make_float4(0.f, 0.f, 0.f, 0.f);
    #pragma unroll
    for (int r = 0; r < 32; r++) {
        float4 v = *(const float4*)&src[(r0 + r) * 128 + c4];
        s4.x += v.x * v.x; s4.y += v.y * v.y;
        s4.z += v.z * v.z; s4.w += v.w * v.w;
        rbuf[2 * r]     = __float22bfloat162_rn(make_float2(v.x, v.y));
        rbuf[2 * r + 1] = __float22bfloat162_rn(make_float2(v.z, v.w));
    }
    __shared__ float4 sred[4][32];
    sred[w][lane] = s4;
    __syncthreads();
    float4 cs;
    {
        float4 a = sred[0][lane], bb = sred[1][lane], c = sred[2][lane], d = sred[3][lane];
        cs = make_float4(a.x + bb.x + c.x + d.x, a.y + bb.y + c.y + d.y,
                         a.z + bb.z + c.z + d.z, a.w + bb.w + c.w + d.w);
    }
    float4 inv = make_float4(1.f / fmaxf(sqrtf(cs.x), 1e-12f),
                             1.f / fmaxf(sqrtf(cs.y), 1e-12f),
                             1.f / fmaxf(sqrtf(cs.z), 1e-12f),
                             1.f / fmaxf(sqrtf(cs.w), 1e-12f));
    float t = cs.x * inv.x * inv.x + cs.y * inv.y * inv.y
            + cs.z * inv.z * inv.z + cs.w * inv.w * inv.w;
    #pragma unroll
    for (int off = 16; off > 0; off >>= 1) t += __shfl_xor_sync(0xFFFFFFFF, t, off);
    const float finv = 1.f / fmaxf(sqrtf(t), 1e-8f);
    const float4 scl = make_float4(inv.x * finv * FP8_SCALE, inv.y * finv * FP8_SCALE,
                                   inv.z * finv * FP8_SCALE, inv.w * finv * FP8_SCALE);

    uint32_t* dst = (uint32_t*)(g_rn + (size_t)b * DFLAT);
    #pragma unroll
    for (int r = 0; r < 32; r++) {
        float2 lo = __bfloat1622float2(rbuf[2 * r]);
        float2 hi = __bfloat1622float2(rbuf[2 * r + 1]);
        uint32_t plo = f2_e4m3x2(lo.y * scl.y, lo.x * scl.x);
        uint32_t phi = f2_e4m3x2(hi.y * scl.w, hi.x * scl.z);
        dst[((r0 + r) * 128 + c4) >> 2] = (phi << 16) | plo;
    }
}

// ---------------- kernel 2: symmetric FP8 (f16-acc) GEMM + fused exp/row-reduce epilogue ----------------
// R11 + fully persistent fragment pipeline: at ks=3 prefetch next STAGE's ks=0
// fragments (CP_WAIT(1) guarantees stage s+1 arrived at step s).
#define BK       128
#define KSTEPS   (DFLAT / BK)          // 128
#define A_B      (128 * 128)           // 16 KB
#define B_B      (64 * 128)            // 8 KB
#define STAGE_B  (A_B + B_B)           // 24 KB
#define NSTAGE   4
#define GSMEM    (NSTAGE * STAGE_B)    // 96 KB -> 2 CTAs/SM

__global__ void __launch_bounds__(256, 2) gemm_kernel() {
    extern __shared__ char sm[];
    const uint32_t sbase = smem_u32(sm);
    const int tid = threadIdx.x;
    const int warp = tid >> 5, lane = tid & 31;
    const int wm = warp >> 1, wn = warp & 1;
    const int g = lane >> 2, tig = lane & 3;

    int t = blockIdx.x >> 1, bm = 0;
    const int half = blockIdx.x & 1;
    while (t >= NBLK - bm) { t -= NBLK - bm; bm++; }
    const int bn = bm + t;
    const bool diag  = (bn == bm);
    const bool ptile = (bn - bm == 8);

    const uint8_t* gA = g_rn + (size_t)(bm * 128) * DFLAT;
    const uint8_t* gB = g_rn + (size_t)(bn * 128 + half * 64) * DFLAT;

    uint32_t acc[2][4][2];
    #pragma unroll
    for (int mt = 0; mt < 2; mt++)
        #pragma unroll
        for (int nt = 0; nt < 4; nt++)
            acc[mt][nt][0] = acc[mt][nt][1] = 0u;

    auto load_stage = [&](int s, int buf) {
        const uint32_t base = sbase + buf * STAGE_B;
        const int k0 = s * BK;
        #pragma unroll
        for (int i = 0; i < 6; i++) {
            int c = tid + i * 256;
            bool isA = (c < 1024);
            int cc  = isA ? c : (c - 1024);
            int row = cc >> 3;
            int cb  = (cc & 7) * 16;
            uint32_t off = row * 128 + (cb ^ ((row & 7) << 4));
            const uint8_t* src = (isA ? gA : gB) + (size_t)row * DFLAT + k0 + cb;
            cpasync16(base + (isA ? 0 : A_B) + off, src);
        }
    };

    load_stage(0, 0); CP_COMMIT();
    load_stage(1, 1); CP_COMMIT();
    load_stage(2, 2); CP_COMMIT();

    const int lrow = lane & 15;
    const int hi   = (lane >> 4) * 16;
    uint32_t aBase[2], aXr[2], bBase[2], bXr[2];
    #pragma unroll
    for (int mt = 0; mt < 2; mt++) {
        int r = wm * 32 + mt * 16 + lrow;
        aBase[mt] = r * 128;  aXr[mt] = (r & 7) << 4;
    }
    #pragma unroll
    for (int p = 0; p < 2; p++) {
        int r = wn * 32 + p * 16 + lrow;
        bBase[p] = A_B + r * 128;  bXr[p] = (r & 7) << 4;
    }

    // ---- persistent fragment double buffers ----
    uint32_t fA0[2][4], fA1[2][4], fB0[2][4], fB1[2][4];

    // prologue: stage 0 arrived (3 commits, wait(1) -> >=2 complete)
    CP_WAIT(1);
    __syncthreads();
    LDSM4(fA0[0][0], fA0[0][1], fA0[0][2], fA0[0][3], sbase + aBase[0] + (hi ^ aXr[0]));
    LDSM4(fA1[0][0], fA1[0][1], fA1[0][2], fA1[0][3], sbase + aBase[1] + (hi ^ aXr[1]));
    LDSM4(fB0[0][0], fB0[0][1], fB0[0][2], fB0[0][3], sbase + bBase[0] + (hi ^ bXr[0]));
    LDSM4(fB1[0][0], fB1[0][1], fB1[0][2], fB1[0][3], sbase + bBase[1] + (hi ^ bXr[1]));

    for (int s = 0; s < KSTEPS; s++) {
        if (s) {
            CP_WAIT(1);            // stages <= s+1 arrived
            __syncthreads();       // all warps done reading buffer (s-1)&3
        }
        if (s + 3 < KSTEPS) load_stage(s + 3, (s + 3) & 3);
        CP_COMMIT();               // empty groups in tail keep wait counts aligned

        const uint32_t stg  = sbase + (s & 3) * STAGE_B;
        const uint32_t stgN = sbase + ((s + 1) & 3) * STAGE_B;

        #pragma unroll
        for (int ks = 0; ks < 4; ks++) {
            const int cur = ks & 1, nxt = cur ^ 1;
            if (ks < 3) {          // prefetch next sub-step of this stage
                const int kb = (ks + 1) * 32 + hi;
                LDSM4(fA0[nxt][0], fA0[nxt][1], fA0[nxt][2], fA0[nxt][3], stg + aBase[0] + (kb ^ aXr[0]));
                LDSM4(fA1[nxt][0], fA1[nxt][1], fA1[nxt][2], fA1[nxt][3], stg + aBase[1] + (kb ^ aXr[1]));
                LDSM4(fB0[nxt][0], fB0[nxt][1], fB0[nxt][2], fB0[nxt][3], stg + bBase[0] + (kb ^ bXr[0]));
                LDSM4(fB1[nxt][0], fB1[nxt][1], fB1[nxt][2], fB1[nxt][3], stg + bBase[1] + (kb ^ bXr[1]));
            } else if (s + 1 < KSTEPS) {   // prefetch NEXT STAGE's ks=0 (data proven arrived)
                LDSM4(fA0[nxt][0], fA0[nxt][1], fA0[nxt][2], fA0[nxt][3], stgN + aBase[0] + (hi ^ aXr[0]));
                LDSM4(fA1[nxt][0], fA1[nxt][1], fA1[nxt][2], fA1[nxt][3], stgN + aBase[1] + (hi ^ aXr[1]));
                LDSM4(fB0[nxt][0], fB0[nxt][1], fB0[nxt][2], fB0[nxt][3], stgN + bBase[0] + (hi ^ bXr[0]));
                LDSM4(fB1[nxt][0], fB1[nxt][1], fB1[nxt][2], fB1[nxt][3], stgN + bBase[1] + (hi ^ bXr[1]));
            }
            #pragma unroll
            for (int nt = 0; nt < 4; nt++) {
                uint32_t b0 = (nt < 2) ? fB0[cur][nt & 1]       : fB1[cur][nt & 1];
                uint32_t b1 = (nt < 2) ? fB0[cur][(nt & 1) + 2] : fB1[cur][(nt & 1) + 2];
                mma16832h(acc[0][nt], fA0[cur], b0, b1);
                mma16832h(acc[1][nt], fA1[cur], b0, b1);
            }
        }
    }

    // fused epilogue: promote f16 accs, v = acc/S^2; e = exp(2v); rows + cols
    float rowp[2][2] = {{0.f, 0.f}, {0.f, 0.f}};
    float colp[4][2];
    #pragma unroll
    for (int nt = 0; nt < 4; nt++) colp[nt][0] = colp[nt][1] = 0.f;

    #pragma unroll
    for (int mt = 0; mt < 2; mt++) {
        const int rl = wm * 32 + mt * 16 + g;
        #pragma unroll
        for (int nt = 0; nt < 4; nt++) {
            const int cg = half * 64 + wn * 32 + nt * 8 + tig * 2;
            float2 f01 = __half22float2(*(const __half2*)&acc[mt][nt][0]);
            float2 f23 = __half22float2(*(const __half2*)&acc[mt][nt][1]);
            float v0 = f01.x * INV_ACC, v1 = f01.y * INV_ACC;
            float v2 = f23.x * INV_ACC, v3 = f23.y * INV_ACC;
            float e0 = __expf(2.f * v0), e1 = __expf(2.f * v1);
            float e2 = __expf(2.f * v2), e3 = __expf(2.f * v3);
            if (diag) {
                if (rl == cg)         e0 = 0.f;
                if (rl == cg + 1)     e1 = 0.f;
                if (rl + 8 == cg)     e2 = 0.f;
                if (rl + 8 == cg + 1) e3 = 0.f;
            }
            if (ptile) {
                int gr = bm * 128 + rl;
                if (rl == cg)         { g_pos[gr]     = v0; g_pos[gr + BATCH]     = v0; }
                if (rl == cg + 1)     { g_pos[gr]     = v1; g_pos[gr + BATCH]     = v1; }
                if (rl + 8 == cg)     { g_pos[gr + 8] = v2; g_pos[gr + 8 + BATCH] = v2; }
                if (rl + 8 == cg + 1) { g_pos[gr + 8] = v3; g_pos[gr + 8 + BATCH] = v3; }
            }
            rowp[mt][0] += e0 + e1;
            rowp[mt][1] += e2 + e3;
            colp[nt][0] += e0 + e2;
            colp[nt][1] += e1 + e3;
        }
    }

    #pragma unroll
    for (int mt = 0; mt < 2; mt++)
        #pragma unroll
        for (int h = 0; h < 2; h++) {
            float v = rowp[mt][h];
            v += __shfl_xor_sync(0xFFFFFFFF, v, 1);
            v += __shfl_xor_sync(0xFFFFFFFF, v, 2);
            if (tig == 0)
                atomicAdd(&g_row[bm * 128 + wm * 32 + mt * 16 + g + h * 8], v);
        }

    if (!diag) {
        #pragma unroll
        for (int nt = 0; nt < 4; nt++)
            #pragma unroll
            for (int q = 0; q < 2; q++) {
                float v = colp[nt][q];
                v += __shfl_xor_sync(0xFFFFFFFF, v, 4);
                v += __shfl_xor_sync(0xFFFFFFFF, v, 8);
                v += __shfl_xor_sync(0xFFFFFFFF, v, 16);
                if (g == 0)
                    atomicAdd(&g_row[bn * 128 + half * 64 + wn * 32 + nt * 8 + tig * 2 + q], v);
            }
    }
}

// ---------------- kernel 3: final scalar ----------------
__global__ void fin_kernel(float* __restrict__ out) {
    float s = 0.f;
    for (int i = threadIdx.x; i < TWO_B; i += 256)
        s += logf(g_row[i]) - 2.f * g_pos[i];
    __shared__ float red[256];
    red[threadIdx.x] = s;
    __syncthreads();
    for (int off = 128; off > 0; off >>= 1) {
        if (threadIdx.x < off) red[threadIdx.x] += red[threadIdx.x + off];
        __syncthreads();
    }
    if (threadIdx.x == 0) out[0] = red[0] / (float)TWO_B;
}

// ---------------- launch ----------------
extern "C" void kernel_launch(void* const* d_in, const int* in_sizes, int n_in,
                              void* d_out, int out_size) {
    const float* ei = (const float*)d_in[0];
    const float* ej = (const float*)d_in[1];
    float* out = (float*)d_out;

    cudaFuncSetAttribute(gemm_kernel, cudaFuncAttributeMaxDynamicSharedMemorySize, GSMEM);

    nrm_kernel<<<TWO_B, 128>>>(ei, ej);
    gemm_kernel<<<272, 256, GSMEM>>>();
    fin_kernel<<<1, 256>>>(out);
}

// round 14
// speedup vs baseline: 1.1885x; 1.0073x over previous
#include <cuda_runtime.h>
#include <cuda_bf16.h>
#include <cuda_fp16.h>
#include <cstdint>

#define BATCH   1024
#define TWO_B   2048
#define DFLAT   16384
#define NBLK    16
#define NCTA    272
#define FP8_SCALE 128.f
#define INV_ACC   (1.f / 16384.f)

// ---------------- scratch ----------------
__device__ uint8_t g_rn[(size_t)TWO_B * DFLAT];   // 32 MB e4m3 (L2-resident)
__device__ float   g_row[TWO_B];
__device__ float   g_pos[TWO_B];
__device__ int     g_done;

// ---------------- helpers ----------------
__device__ __forceinline__ uint32_t smem_u32(const void* p) {
    return (uint32_t)__cvta_generic_to_shared(p);
}
__device__ __forceinline__ void cpasync16(uint32_t s, const void* g) {
    asm volatile("cp.async.ca.shared.global [%0], [%1], 16;\n" :: "r"(s), "l"(g));
}
#define CP_COMMIT() asm volatile("cp.async.commit_group;\n")
#define CP_WAIT(N)  asm volatile("cp.async.wait_group %0;\n" :: "n"(N))

#define LDSM4(r0, r1, r2, r3, a) \
    asm volatile("ldmatrix.sync.aligned.m8n8.x4.shared.b16 {%0,%1,%2,%3}, [%4];" \
                 : "=r"(r0), "=r"(r1), "=r"(r2), "=r"(r3) : "r"(a))

// fp8 e4m3 mma with f16 accumulators (fastest register path measured on sm_103a)
__device__ __forceinline__ void mma16832h(uint32_t* c, const uint32_t* a, uint32_t b0, uint32_t b1) {
    asm volatile(
        "mma.sync.aligned.m16n8k32.row.col.f16.e4m3.e4m3.f16 "
        "{%0,%1}, {%2,%3,%4,%5}, {%6,%7}, {%0,%1};\n"
        : "+r"(c[0]), "+r"(c[1])
        : "r"(a[0]), "r"(a[1]), "r"(a[2]), "r"(a[3]), "r"(b0), "r"(b1));
}

__device__ __forceinline__ uint32_t f2_e4m3x2(float hi, float lo) {
    uint16_t r;
    asm volatile("cvt.rn.satfinite.e4m3x2.f32 %0, %1, %2;" : "=h"(r) : "f"(hi), "f"(lo));
    return (uint32_t)r;
}

// ---------------- kernel 1: fused double normalization -> scaled e4m3 (proven) ----------------
__global__ void __launch_bounds__(128) nrm_kernel(const float* __restrict__ ei,
                                                  const float* __restrict__ ej) {
    const int b = blockIdx.x;
    const float* src = (b < BATCH) ? (ei + (size_t)b * DFLAT)
                                   : (ej + (size_t)(b - BATCH) * DFLAT);
    const int tid = threadIdx.x;
    const int w = tid >> 5, lane = tid & 31;
    const int c4 = lane * 4;
    const int r0 = w * 32;
    if (tid == 0) g_row[b] = 0.f;

    __nv_bfloat162 rbuf[64];
    float4 s4 = make_float4(0.f, 0.f, 0.f, 0.f);
    #pragma unroll
    for (int r = 0; r < 32; r++) {
        float4 v = *(const float4*)&src[(r0 + r) * 128 + c4];
        s4.x += v.x * v.x; s4.y += v.y * v.y;
        s4.z += v.z * v.z; s4.w += v.w * v.w;
        rbuf[2 * r]     = __float22bfloat162_rn(make_float2(v.x, v.y));
        rbuf[2 * r + 1] = __float22bfloat162_rn(make_float2(v.z, v.w));
    }
    __shared__ float4 sred[4][32];
    sred[w][lane] = s4;
    __syncthreads();
    float4 cs;
    {
        float4 a = sred[0][lane], bb = sred[1][lane], c = sred[2][lane], d = sred[3][lane];
        cs = make_float4(a.x + bb.x + c.x + d.x, a.y + bb.y + c.y + d.y,
                         a.z + bb.z + c.z + d.z, a.w + bb.w + c.w + d.w);
    }
    float4 inv = make_float4(1.f / fmaxf(sqrtf(cs.x), 1e-12f),
                             1.f / fmaxf(sqrtf(cs.y), 1e-12f),
                             1.f / fmaxf(sqrtf(cs.z), 1e-12f),
                             1.f / fmaxf(sqrtf(cs.w), 1e-12f));
    float t = cs.x * inv.x * inv.x + cs.y * inv.y * inv.y
            + cs.z * inv.z * inv.z + cs.w * inv.w * inv.w;
    #pragma unroll
    for (int off = 16; off > 0; off >>= 1) t += __shfl_xor_sync(0xFFFFFFFF, t, off);
    const float finv = 1.f / fmaxf(sqrtf(t), 1e-8f);
    const float4 scl = make_float4(inv.x * finv * FP8_SCALE, inv.y * finv * FP8_SCALE,
                                   inv.z * finv * FP8_SCALE, inv.w * finv * FP8_SCALE);

    uint32_t* dst = (uint32_t*)(g_rn + (size_t)b * DFLAT);
    #pragma unroll
    for (int r = 0; r < 32; r++) {
        float2 lo = __bfloat1622float2(rbuf[2 * r]);
        float2 hi = __bfloat1622float2(rbuf[2 * r + 1]);
        uint32_t plo = f2_e4m3x2(lo.y * scl.y, lo.x * scl.x);
        uint32_t phi = f2_e4m3x2(hi.y * scl.w, hi.x * scl.z);
        dst[((r0 + r) * 128 + c4) >> 2] = (phi << 16) | plo;
    }
}

// ---------------- kernel 2: symmetric FP8 (f16-acc) GEMM + fused epilogue + last-CTA final ----------------
// R12 champion mainloop (persistent fragment pipeline) + fin folded via ticket.
#define BK       128
#define KSTEPS   (DFLAT / BK)          // 128
#define A_B      (128 * 128)           // 16 KB
#define B_B      (64 * 128)            // 8 KB
#define STAGE_B  (A_B + B_B)           // 24 KB
#define NSTAGE   4
#define GSMEM    (NSTAGE * STAGE_B)    // 96 KB -> 2 CTAs/SM

__global__ void __launch_bounds__(256, 2) gemm_kernel(float* __restrict__ out) {
    extern __shared__ char sm[];
    const uint32_t sbase = smem_u32(sm);
    const int tid = threadIdx.x;
    const int warp = tid >> 5, lane = tid & 31;
    const int wm = warp >> 1, wn = warp & 1;
    const int g = lane >> 2, tig = lane & 3;

    int t = blockIdx.x >> 1, bm = 0;
    const int half = blockIdx.x & 1;
    while (t >= NBLK - bm) { t -= NBLK - bm; bm++; }
    const int bn = bm + t;
    const bool diag  = (bn == bm);
    const bool ptile = (bn - bm == 8);

    const uint8_t* gA = g_rn + (size_t)(bm * 128) * DFLAT;
    const uint8_t* gB = g_rn + (size_t)(bn * 128 + half * 64) * DFLAT;

    uint32_t acc[2][4][2];
    #pragma unroll
    for (int mt = 0; mt < 2; mt++)
        #pragma unroll
        for (int nt = 0; nt < 4; nt++)
            acc[mt][nt][0] = acc[mt][nt][1] = 0u;

    auto load_stage = [&](int s, int buf) {
        const uint32_t base = sbase + buf * STAGE_B;
        const int k0 = s * BK;
        #pragma unroll
        for (int i = 0; i < 6; i++) {
            int c = tid + i * 256;
            bool isA = (c < 1024);
            int cc  = isA ? c : (c - 1024);
            int row = cc >> 3;
            int cb  = (cc & 7) * 16;
            uint32_t off = row * 128 + (cb ^ ((row & 7) << 4));
            const uint8_t* src = (isA ? gA : gB) + (size_t)row * DFLAT + k0 + cb;
            cpasync16(base + (isA ? 0 : A_B) + off, src);
        }
    };

    load_stage(0, 0); CP_COMMIT();
    load_stage(1, 1); CP_COMMIT();
    load_stage(2, 2); CP_COMMIT();

    const int lrow = lane & 15;
    const int hi   = (lane >> 4) * 16;
    uint32_t aBase[2], aXr[2], bBase[2], bXr[2];
    #pragma unroll
    for (int mt = 0; mt < 2; mt++) {
        int r = wm * 32 + mt * 16 + lrow;
        aBase[mt] = r * 128;  aXr[mt] = (r & 7) << 4;
    }
    #pragma unroll
    for (int p = 0; p < 2; p++) {
        int r = wn * 32 + p * 16 + lrow;
        bBase[p] = A_B + r * 128;  bXr[p] = (r & 7) << 4;
    }

    // ---- persistent fragment double buffers ----
    uint32_t fA0[2][4], fA1[2][4], fB0[2][4], fB1[2][4];

    CP_WAIT(1);
    __syncthreads();
    LDSM4(fA0[0][0], fA0[0][1], fA0[0][2], fA0[0][3], sbase + aBase[0] + (hi ^ aXr[0]));
    LDSM4(fA1[0][0], fA1[0][1], fA1[0][2], fA1[0][3], sbase + aBase[1] + (hi ^ aXr[1]));
    LDSM4(fB0[0][0], fB0[0][1], fB0[0][2], fB0[0][3], sbase + bBase[0] + (hi ^ bXr[0]));
    LDSM4(fB1[0][0], fB1[0][1], fB1[0][2], fB1[0][3], sbase + bBase[1] + (hi ^ bXr[1]));

    for (int s = 0; s < KSTEPS; s++) {
        if (s) {
            CP_WAIT(1);            // stages <= s+1 arrived
            __syncthreads();       // all warps done reading buffer (s-1)&3
        }
        if (s + 3 < KSTEPS) load_stage(s + 3, (s + 3) & 3);
        CP_COMMIT();               // empty groups in tail keep wait counts aligned

        const uint32_t stg  = sbase + (s & 3) * STAGE_B;
        const uint32_t stgN = sbase + ((s + 1) & 3) * STAGE_B;

        #pragma unroll
        for (int ks = 0; ks < 4; ks++) {
            const int cur = ks & 1, nxt = cur ^ 1;
            if (ks < 3) {
                const int kb = (ks + 1) * 32 + hi;
                LDSM4(fA0[nxt][0], fA0[nxt][1], fA0[nxt][2], fA0[nxt][3], stg + aBase[0] + (kb ^ aXr[0]));
                LDSM4(fA1[nxt][0], fA1[nxt][1], fA1[nxt][2], fA1[nxt][3], stg + aBase[1] + (kb ^ aXr[1]));
                LDSM4(fB0[nxt][0], fB0[nxt][1], fB0[nxt][2], fB0[nxt][3], stg + bBase[0] + (kb ^ bXr[0]));
                LDSM4(fB1[nxt][0], fB1[nxt][1], fB1[nxt][2], fB1[nxt][3], stg + bBase[1] + (kb ^ bXr[1]));
            } else if (s + 1 < KSTEPS) {
                LDSM4(fA0[nxt][0], fA0[nxt][1], fA0[nxt][2], fA0[nxt][3], stgN + aBase[0] + (hi ^ aXr[0]));
                LDSM4(fA1[nxt][0], fA1[nxt][1], fA1[nxt][2], fA1[nxt][3], stgN + aBase[1] + (hi ^ aXr[1]));
                LDSM4(fB0[nxt][0], fB0[nxt][1], fB0[nxt][2], fB0[nxt][3], stgN + bBase[0] + (hi ^ bXr[0]));
                LDSM4(fB1[nxt][0], fB1[nxt][1], fB1[nxt][2], fB1[nxt][3], stgN + bBase[1] + (hi ^ bXr[1]));
            }
            #pragma unroll
            for (int nt = 0; nt < 4; nt++) {
                uint32_t b0 = (nt < 2) ? fB0[cur][nt & 1]       : fB1[cur][nt & 1];
                uint32_t b1 = (nt < 2) ? fB0[cur][(nt & 1) + 2] : fB1[cur][(nt & 1) + 2];
                mma16832h(acc[0][nt], fA0[cur], b0, b1);
                mma16832h(acc[1][nt], fA1[cur], b0, b1);
            }
        }
    }

    // fused epilogue
    float rowp[2][2] = {{0.f, 0.f}, {0.f, 0.f}};
    float colp[4][2];
    #pragma unroll
    for (int nt = 0; nt < 4; nt++) colp[nt][0] = colp[nt][1] = 0.f;

    #pragma unroll
    for (int mt = 0; mt < 2; mt++) {
        const int rl = wm * 32 + mt * 16 + g;
        #pragma unroll
        for (int nt = 0; nt < 4; nt++) {
            const int cg = half * 64 + wn * 32 + nt * 8 + tig * 2;
            float2 f01 = __half22float2(*(const __half2*)&acc[mt][nt][0]);
            float2 f23 = __half22float2(*(const __half2*)&acc[mt][nt][1]);
            float v0 = f01.x * INV_ACC, v1 = f01.y * INV_ACC;
            float v2 = f23.x * INV_ACC, v3 = f23.y * INV_ACC;
            float e0 = __expf(2.f * v0), e1 = __expf(2.f * v1);
            float e2 = __expf(2.f * v2), e3 = __expf(2.f * v3);
            if (diag) {
                if (rl == cg)         e0 = 0.f;
                if (rl == cg + 1)     e1 = 0.f;
                if (rl + 8 == cg)     e2 = 0.f;
                if (rl + 8 == cg + 1) e3 = 0.f;
            }
            if (ptile) {
                int gr = bm * 128 + rl;
                if (rl == cg)         { g_pos[gr]     = v0; g_pos[gr + BATCH]     = v0; }
                if (rl == cg + 1)     { g_pos[gr]     = v1; g_pos[gr + BATCH]     = v1; }
                if (rl + 8 == cg)     { g_pos[gr + 8] = v2; g_pos[gr + 8 + BATCH] = v2; }
                if (rl + 8 == cg + 1) { g_pos[gr + 8] = v3; g_pos[gr + 8 + BATCH] = v3; }
            }
            rowp[mt][0] += e0 + e1;
            rowp[mt][1] += e2 + e3;
            colp[nt][0] += e0 + e2;
            colp[nt][1] += e1 + e3;
        }
    }

    #pragma unroll
    for (int mt = 0; mt < 2; mt++)
        #pragma unroll
        for (int h = 0; h < 2; h++) {
            float v = rowp[mt][h];
            v += __shfl_xor_sync(0xFFFFFFFF, v, 1);
            v += __shfl_xor_sync(0xFFFFFFFF, v, 2);
            if (tig == 0)
                atomicAdd(&g_row[bm * 128 + wm * 32 + mt * 16 + g + h * 8], v);
        }

    if (!diag) {
        #pragma unroll
        for (int nt = 0; nt < 4; nt++)
            #pragma unroll
            for (int q = 0; q < 2; q++) {
                float v = colp[nt][q];
                v += __shfl_xor_sync(0xFFFFFFFF, v, 4);
                v += __shfl_xor_sync(0xFFFFFFFF, v, 8);
                v += __shfl_xor_sync(0xFFFFFFFF, v, 16);
                if (g == 0)
                    atomicAdd(&g_row[bn * 128 + half * 64 + wn * 32 + nt * 8 + tig * 2 + q], v);
            }
    }

    // ---- last-CTA ticket: inline final reduction (replaces fin kernel) ----
    __threadfence();
    __syncthreads();
    __shared__ int is_last;
    if (tid == 0) is_last = (atomicAdd(&g_done, 1) == NCTA - 1) ? 1 : 0;
    __syncthreads();
    if (is_last) {
        __threadfence();                       // observe all other CTAs' g_row atomics
        float s = 0.f;
        #pragma unroll
        for (int k = 0; k < 8; k++) {
            int i = tid + k * 256;
            s += logf(g_row[i]) - 2.f * g_pos[i];
        }
        float* red = (float*)sm;
        red[tid] = s;
        __syncthreads();
        for (int off = 128; off > 0; off >>= 1) {
            if (tid < off) red[tid] += red[tid + off];
            __syncthreads();
        }
        if (tid == 0) {
            out[0] = red[0] / (float)TWO_B;
            g_done = 0;                        // reset for next graph replay
            __threadfence();
        }
    }
}

// ---------------- launch ----------------
extern "C" void kernel_launch(void* const* d_in, const int* in_sizes, int n_in,
                              void* d_out, int out_size) {
    const float* ei = (const float*)d_in[0];
    const float* ej = (const float*)d_in[1];
    float* out = (float*)d_out;

    cudaFuncSetAttribute(gemm_kernel, cudaFuncAttributeMaxDynamicSharedMemorySize, GSMEM);

    nrm_kernel<<<TWO_B, 128>>>(ei, ej);
    gemm_kernel<<<NCTA, 256, GSMEM>>>(out);
}

// round 15
// speedup vs baseline: 1.2123x; 1.0200x over previous
#include <cuda_runtime.h>
#include <cuda_bf16.h>
#include <cuda_fp16.h>
#include <cstdint>

#define BATCH   1024
#define TWO_B   2048
#define DFLAT   16384
#define NBLK    16
#define NCTA    136
#define FP8_SCALE 128.f
#define INV_ACC   (1.f / 16384.f)

// ---------------- scratch ----------------
__device__ uint8_t g_rn[(size_t)TWO_B * DFLAT];   // 32 MB e4m3 (L2-resident)
__device__ float   g_row[TWO_B];
__device__ float   g_pos[TWO_B];
__device__ int     g_done;

// ---------------- helpers ----------------
__device__ __forceinline__ uint32_t smem_u32(const void* p) {
    return (uint32_t)__cvta_generic_to_shared(p);
}
__device__ __forceinline__ void cpasync16(uint32_t s, const void* g) {
    asm volatile("cp.async.ca.shared.global [%0], [%1], 16;\n" :: "r"(s), "l"(g));
}
#define CP_COMMIT() asm volatile("cp.async.commit_group;\n")
#define CP_WAIT(N)  asm volatile("cp.async.wait_group %0;\n" :: "n"(N))

#define LDSM4(r0, r1, r2, r3, a) \
    asm volatile("ldmatrix.sync.aligned.m8n8.x4.shared.b16 {%0,%1,%2,%3}, [%4];" \
                 : "=r"(r0), "=r"(r1), "=r"(r2), "=r"(r3) : "r"(a))

// fp8 e4m3 mma with f16 accumulators (fastest register path measured on sm_103a)
__device__ __forceinline__ void mma16832h(uint32_t* c, const uint32_t* a, uint32_t b0, uint32_t b1) {
    asm volatile(
        "mma.sync.aligned.m16n8k32.row.col.f16.e4m3.e4m3.f16 "
        "{%0,%1}, {%2,%3,%4,%5}, {%6,%7}, {%0,%1};\n"
        : "+r"(c[0]), "+r"(c[1])
        : "r"(a[0]), "r"(a[1]), "r"(a[2]), "r"(a[3]), "r"(b0), "r"(b1));
}

__device__ __forceinline__ uint32_t f2_e4m3x2(float hi, float lo) {
    uint16_t r;
    asm volatile("cvt.rn.satfinite.e4m3x2.f32 %0, %1, %2;" : "=h"(r) : "f"(hi), "f"(lo));
    return (uint32_t)r;
}

// ---------------- kernel 1: fused double normalization -> scaled e4m3 (proven) ----------------
__global__ void __launch_bounds__(128) nrm_kernel(const float* __restrict__ ei,
                                                  const float* __restrict__ ej) {
    const int b = blockIdx.x;
    const float* src = (b < BATCH) ? (ei + (size_t)b * DFLAT)
                                   : (ej + (size_t)(b - BATCH) * DFLAT);
    const int tid = threadIdx.x;
    const int w = tid >> 5, lane = tid & 31;
    const int c4 = lane * 4;
    const int r0 = w * 32;
    if (tid == 0) g_row[b] = 0.f;

    __nv_bfloat162 rbuf[64];
    float4 s4 = make_float4(0.f, 0.f, 0.f, 0.f);
    #pragma unroll
    for (int r = 0; r < 32; r++) {
        float4 v = *(const float4*)&src[(r0 + r) * 128 + c4];
        s4.x += v.x * v.x; s4.y += v.y * v.y;
        s4.z += v.z * v.z; s4.w += v.w * v.w;
        rbuf[2 * r]     = __float22bfloat162_rn(make_float2(v.x, v.y));
        rbuf[2 * r + 1] = __float22bfloat162_rn(make_float2(v.z, v.w));
    }
    __shared__ float4 sred[4][32];
    sred[w][lane] = s4;
    __syncthreads();
    float4 cs;
    {
        float4 a = sred[0][lane], bb = sred[1][lane], c = sred[2][lane], d = sred[3][lane];
        cs = make_float4(a.x + bb.x + c.x + d.x, a.y + bb.y + c.y + d.y,
                         a.z + bb.z + c.z + d.z, a.w + bb.w + c.w + d.w);
    }
    float4 inv = make_float4(1.f / fmaxf(sqrtf(cs.x), 1e-12f),
                             1.f / fmaxf(sqrtf(cs.y), 1e-12f),
                             1.f / fmaxf(sqrtf(cs.z), 1e-12f),
                             1.f / fmaxf(sqrtf(cs.w), 1e-12f));
    float t = cs.x * inv.x * inv.x + cs.y * inv.y * inv.y
            + cs.z * inv.z * inv.z + cs.w * inv.w * inv.w;
    #pragma unroll
    for (int off = 16; off > 0; off >>= 1) t += __shfl_xor_sync(0xFFFFFFFF, t, off);
    const float finv = 1.f / fmaxf(sqrtf(t), 1e-8f);
    const float4 scl = make_float4(inv.x * finv * FP8_SCALE, inv.y * finv * FP8_SCALE,
                                   inv.z * finv * FP8_SCALE, inv.w * finv * FP8_SCALE);

    uint32_t* dst = (uint32_t*)(g_rn + (size_t)b * DFLAT);
    #pragma unroll
    for (int r = 0; r < 32; r++) {
        float2 lo = __bfloat1622float2(rbuf[2 * r]);
        float2 hi = __bfloat1622float2(rbuf[2 * r + 1]);
        uint32_t plo = f2_e4m3x2(lo.y * scl.y, lo.x * scl.x);
        uint32_t phi = f2_e4m3x2(hi.y * scl.w, hi.x * scl.z);
        dst[((r0 + r) * 128 + c4) >> 2] = (phi << 16) | plo;
    }
}

// ---------------- kernel 2: symmetric FP8 (f16-acc) GEMM, tile 128x128, warp tile 32x64 ----------------
// 136 CTAs = upper-triangle tiles. MMA:LDSM ratio 2.67 (16 MMA per 6 LDSM4 per sub-step).
// Persistent fragment pipeline (R12) + last-CTA fin fold (R13).
#define BK       128
#define KSTEPS   (DFLAT / BK)          // 128
#define A_B      (128 * 128)           // 16 KB
#define B_B      (128 * 128)           // 16 KB (full 128-col tile)
#define STAGE_B  (A_B + B_B)           // 32 KB
#define NSTAGE   4
#define GSMEM    (NSTAGE * STAGE_B)    // 128 KB -> 1 CTA/SM, regs up to 255

__global__ void __launch_bounds__(256, 1) gemm_kernel(float* __restrict__ out) {
    extern __shared__ char sm[];
    const uint32_t sbase = smem_u32(sm);
    const int tid = threadIdx.x;
    const int warp = tid >> 5, lane = tid & 31;
    const int wm = warp >> 1, wn = warp & 1;     // 4 x 2 warp grid; warp tile 32x64
    const int g = lane >> 2, tig = lane & 3;

    int t = blockIdx.x, bm = 0;
    while (t >= NBLK - bm) { t -= NBLK - bm; bm++; }
    const int bn = bm + t;
    const bool diag  = (bn == bm);
    const bool ptile = (bn - bm == 8);

    const uint8_t* gA = g_rn + (size_t)(bm * 128) * DFLAT;
    const uint8_t* gB = g_rn + (size_t)(bn * 128) * DFLAT;

    uint32_t acc[2][8][2];
    #pragma unroll
    for (int mt = 0; mt < 2; mt++)
        #pragma unroll
        for (int nt = 0; nt < 8; nt++)
            acc[mt][nt][0] = acc[mt][nt][1] = 0u;

    // stage loader: 2048 x 16B chunks, 8 per thread (A first 1024, B second)
    auto load_stage = [&](int s, int buf) {
        const uint32_t base = sbase + buf * STAGE_B;
        const int k0 = s * BK;
        #pragma unroll
        for (int i = 0; i < 8; i++) {
            int c = tid + i * 256;
            bool isA = (c < 1024);
            int cc  = isA ? c : (c - 1024);
            int row = cc >> 3;
            int cb  = (cc & 7) * 16;
            uint32_t off = row * 128 + (cb ^ ((row & 7) << 4));
            const uint8_t* src = (isA ? gA : gB) + (size_t)row * DFLAT + k0 + cb;
            cpasync16(base + (isA ? 0 : A_B) + off, src);
        }
    };

    load_stage(0, 0); CP_COMMIT();
    load_stage(1, 1); CP_COMMIT();
    load_stage(2, 2); CP_COMMIT();

    const int lrow = lane & 15;
    const int hi   = (lane >> 4) * 16;
    uint32_t aBase[2], aXr[2], bBase[4], bXr[4];
    #pragma unroll
    for (int mt = 0; mt < 2; mt++) {
        int r = wm * 32 + mt * 16 + lrow;
        aBase[mt] = r * 128;  aXr[mt] = (r & 7) << 4;
    }
    #pragma unroll
    for (int p = 0; p < 4; p++) {
        int r = wn * 64 + p * 16 + lrow;
        bBase[p] = A_B + r * 128;  bXr[p] = (r & 7) << 4;
    }

    // ---- persistent fragment double buffers ----
    uint32_t fA[2][2][4];      // [mt][buf][4]
    uint32_t fB[2][4][4];      // [buf][p][4]

    CP_WAIT(1);
    __syncthreads();
    #pragma unroll
    for (int mt = 0; mt < 2; mt++)
        LDSM4(fA[mt][0][0], fA[mt][0][1], fA[mt][0][2], fA[mt][0][3],
              sbase + aBase[mt] + (hi ^ aXr[mt]));
    #pragma unroll
    for (int p = 0; p < 4; p++)
        LDSM4(fB[0][p][0], fB[0][p][1], fB[0][p][2], fB[0][p][3],
              sbase + bBase[p] + (hi ^ bXr[p]));

    for (int s = 0; s < KSTEPS; s++) {
        if (s) {
            CP_WAIT(1);            // stages <= s+1 arrived
            __syncthreads();       // all warps done reading buffer (s-1)&3
        }
        if (s + 3 < KSTEPS) load_stage(s + 3, (s + 3) & 3);
        CP_COMMIT();               // empty groups in tail keep wait counts aligned

        const uint32_t stg  = sbase + (s & 3) * STAGE_B;
        const uint32_t stgN = sbase + ((s + 1) & 3) * STAGE_B;

        #pragma unroll
        for (int ks = 0; ks < 4; ks++) {
            const int cur = ks & 1, nxt = cur ^ 1;
            if (ks < 3) {          // prefetch next sub-step of this stage
                const int kb = (ks + 1) * 32 + hi;
                #pragma unroll
                for (int mt = 0; mt < 2; mt++)
                    LDSM4(fA[mt][nxt][0], fA[mt][nxt][1], fA[mt][nxt][2], fA[mt][nxt][3],
                          stg + aBase[mt] + (kb ^ aXr[mt]));
                #pragma unroll
                for (int p = 0; p < 4; p++)
                    LDSM4(fB[nxt][p][0], fB[nxt][p][1], fB[nxt][p][2], fB[nxt][p][3],
                          stg + bBase[p] + (kb ^ bXr[p]));
            } else if (s + 1 < KSTEPS) {   // prefetch NEXT STAGE's ks=0
                #pragma unroll
                for (int mt = 0; mt < 2; mt++)
                    LDSM4(fA[mt][nxt][0], fA[mt][nxt][1], fA[mt][nxt][2], fA[mt][nxt][3],
                          stgN + aBase[mt] + (hi ^ aXr[mt]));
                #pragma unroll
                for (int p = 0; p < 4; p++)
                    LDSM4(fB[nxt][p][0], fB[nxt][p][1], fB[nxt][p][2], fB[nxt][p][3],
                          stgN + bBase[p] + (hi ^ bXr[p]));
            }
            #pragma unroll
            for (int nt = 0; nt < 8; nt++) {
                uint32_t b0 = fB[cur][nt >> 1][nt & 1];
                uint32_t b1 = fB[cur][nt >> 1][(nt & 1) + 2];
                mma16832h(acc[0][nt], fA[0][cur], b0, b1);
                mma16832h(acc[1][nt], fA[1][cur], b0, b1);
            }
        }
    }

    // fused epilogue (R3 full-tile indexing)
    float rowp[2][2] = {{0.f, 0.f}, {0.f, 0.f}};
    float colp[8][2];
    #pragma unroll
    for (int nt = 0; nt < 8; nt++) colp[nt][0] = colp[nt][1] = 0.f;

    #pragma unroll
    for (int mt = 0; mt < 2; mt++) {
        const int rl = wm * 32 + mt * 16 + g;
        #pragma unroll
        for (int nt = 0; nt < 8; nt++) {
            const int cl = wn * 64 + nt * 8 + tig * 2;
            float2 f01 = __half22float2(*(const __half2*)&acc[mt][nt][0]);
            float2 f23 = __half22float2(*(const __half2*)&acc[mt][nt][1]);
            float v0 = f01.x * INV_ACC, v1 = f01.y * INV_ACC;
            float v2 = f23.x * INV_ACC, v3 = f23.y * INV_ACC;
            float e0 = __expf(2.f * v0), e1 = __expf(2.f * v1);
            float e2 = __expf(2.f * v2), e3 = __expf(2.f * v3);
            if (diag) {
                if (rl == cl)         e0 = 0.f;
                if (rl == cl + 1)     e1 = 0.f;
                if (rl + 8 == cl)     e2 = 0.f;
                if (rl + 8 == cl + 1) e3 = 0.f;
            }
            if (ptile) {
                int gr = bm * 128 + rl;
                if (rl == cl)         { g_pos[gr]     = v0; g_pos[gr + BATCH]     = v0; }
                if (rl == cl + 1)     { g_pos[gr]     = v1; g_pos[gr + BATCH]     = v1; }
                if (rl + 8 == cl)     { g_pos[gr + 8] = v2; g_pos[gr + 8 + BATCH] = v2; }
                if (rl + 8 == cl + 1) { g_pos[gr + 8] = v3; g_pos[gr + 8 + BATCH] = v3; }
            }
            rowp[mt][0] += e0 + e1;
            rowp[mt][1] += e2 + e3;
            colp[nt][0] += e0 + e2;
            colp[nt][1] += e1 + e3;
        }
    }

    #pragma unroll
    for (int mt = 0; mt < 2; mt++)
        #pragma unroll
        for (int h = 0; h < 2; h++) {
            float v = rowp[mt][h];
            v += __shfl_xor_sync(0xFFFFFFFF, v, 1);
            v += __shfl_xor_sync(0xFFFFFFFF, v, 2);
            if (tig == 0)
                atomicAdd(&g_row[bm * 128 + wm * 32 + mt * 16 + g + h * 8], v);
        }

    if (!diag) {
        #pragma unroll
        for (int nt = 0; nt < 8; nt++)
            #pragma unroll
            for (int q = 0; q < 2; q++) {
                float v = colp[nt][q];
                v += __shfl_xor_sync(0xFFFFFFFF, v, 4);
                v += __shfl_xor_sync(0xFFFFFFFF, v, 8);
                v += __shfl_xor_sync(0xFFFFFFFF, v, 16);
                if (g == 0)
                    atomicAdd(&g_row[bn * 128 + wn * 64 + nt * 8 + tig * 2 + q], v);
            }
    }

    // ---- last-CTA ticket: inline final reduction ----
    __threadfence();
    __syncthreads();
    __shared__ int is_last;
    if (tid == 0) is_last = (atomicAdd(&g_done, 1) == NCTA - 1) ? 1 : 0;
    __syncthreads();
    if (is_last) {
        __threadfence();
        float s = 0.f;
        #pragma unroll
        for (int k = 0; k < 8; k++) {
            int i = tid + k * 256;
            s += logf(g_row[i]) - 2.f * g_pos[i];
        }
        float* red = (float*)sm;
        red[tid] = s;
        __syncthreads();
        for (int off = 128; off > 0; off >>= 1) {
            if (tid < off) red[tid] += red[tid + off];
            __syncthreads();
        }
        if (tid == 0) {
            out[0] = red[0] / (float)TWO_B;
            g_done = 0;
            __threadfence();
        }
    }
}

// ---------------- launch ----------------
extern "C" void kernel_launch(void* const* d_in, const int* in_sizes, int n_in,
                              void* d_out, int out_size) {
    const float* ei = (const float*)d_in[0];
    const float* ej = (const float*)d_in[1];
    float* out = (float*)d_out;

    cudaFuncSetAttribute(gemm_kernel, cudaFuncAttributeMaxDynamicSharedMemorySize, GSMEM);

    nrm_kernel<<<TWO_B, 128>>>(ei, ej);
    gemm_kernel<<<NCTA, 256, GSMEM>>>(out);
}